// round 3
// baseline (speedup 1.0000x reference)
#include <cuda_runtime.h>
#include <cstdint>

#define FEAT 4096
#define BATCH 2048
#define TI 128     // output-feature tile (i)
#define TB 128     // batch tile
#define TK 16      // k-chunk (j)
#define GUARD 128  // zero guard in front of kernel for negative i-j

// shared kernel with zero guard: ksh[GUARD + d] = kernel[d], ksh[0..GUARD) = 0
// max index used: GUARD + (i - j) <= 128 + 4095 = 4223
#define KSH_SIZE (GUARD + FEAT)

__global__ __launch_bounds__(256, 2)
void toeplitz_gemm_kernel(const float* __restrict__ x,
                          const float* __restrict__ kern,
                          float* __restrict__ out)
{
    __shared__ __align__(16) float ksh[KSH_SIZE];
    __shared__ __align__(16) float xs[TK][TB];

    const int tx = threadIdx.x;          // 0..15 -> n (output feature) lanes
    const int ty = threadIdx.y;          // 0..15 -> m (batch) groups
    const int tid = ty * 16 + tx;

    // heavy i-tiles first (i_tile 31 has 256 k-iters, i_tile 0 has 8)
    const int i0 = (31 - (int)blockIdx.x) * TI;
    const int b0 = (int)blockIdx.y * TB;

    // ---- load full kernel into shared (once), zero guard ----
    for (int t = tid; t < GUARD; t += 256) ksh[t] = 0.0f;
    {
        const float4* ksrc = reinterpret_cast<const float4*>(kern);
        float4* kdst = reinterpret_cast<float4*>(&ksh[GUARD]);
        #pragma unroll
        for (int t = 0; t < FEAT / 4 / 256; ++t)
            kdst[tid + t * 256] = ksrc[tid + t * 256];
    }

    // ---- accumulators: 4 batch-pairs x 8 n values, packed f32x2 along batch ----
    unsigned long long acc[4][8];
    #pragma unroll
    for (int s = 0; s < 4; ++s)
        #pragma unroll
        for (int r = 0; r < 8; ++r) acc[s][r] = 0ULL;

    // prefetch mapping: each thread owns (row = tid&127, kg = tid>>7) and (row, kg+2)
    const int prow = tid & 127;
    const int pkg  = tid >> 7;  // 0 or 1
    const float* xrow = x + (size_t)(b0 + prow) * FEAT;

    const int jend = i0 + TI;   // causal: only j < i0 + TI contributes

    // initial prefetch (j0 = 0)
    float4 pre0 = *reinterpret_cast<const float4*>(xrow + pkg * 4);
    float4 pre1 = *reinterpret_cast<const float4*>(xrow + (pkg + 2) * 4);

    for (int j0 = 0; j0 < jend; j0 += TK) {
        // store prefetched x tile (transposed) into shared
        xs[pkg * 4 + 0][prow] = pre0.x;
        xs[pkg * 4 + 1][prow] = pre0.y;
        xs[pkg * 4 + 2][prow] = pre0.z;
        xs[pkg * 4 + 3][prow] = pre0.w;
        xs[(pkg + 2) * 4 + 0][prow] = pre1.x;
        xs[(pkg + 2) * 4 + 1][prow] = pre1.y;
        xs[(pkg + 2) * 4 + 2][prow] = pre1.z;
        xs[(pkg + 2) * 4 + 3][prow] = pre1.w;
        __syncthreads();

        // prefetch next tile while computing this one
        const int j0n = j0 + TK;
        if (j0n < jend) {
            pre0 = *reinterpret_cast<const float4*>(xrow + j0n + pkg * 4);
            pre1 = *reinterpret_cast<const float4*>(xrow + j0n + (pkg + 2) * 4);
        }

        // base index into ksh for this thread: GUARD + (i - j) with i = i0 + tx + 16r, j = j0 + kk
        const int nbase = GUARD + i0 + tx - j0;

        #pragma unroll
        for (int kk = 0; kk < TK; ++kk) {
            const float* krow = &ksh[nbase - kk];

            // B fragment: kernel values, broadcast-packed into f32x2
            unsigned long long b2[8];
            #pragma unroll
            for (int r = 0; r < 8; ++r) {
                float bv = krow[16 * r];
                asm("mov.b64 %0, {%1, %1};" : "=l"(b2[r]) : "f"(bv));
            }

            // A fragment: aligned float2 (two adjacent batch rows), broadcast across tx
            #pragma unroll
            for (int s = 0; s < 4; ++s) {
                unsigned long long a2 =
                    *reinterpret_cast<const unsigned long long*>(&xs[kk][ty * 8 + 2 * s]);
                #pragma unroll
                for (int r = 0; r < 8; ++r) {
                    asm("fma.rn.f32x2 %0, %1, %2, %0;"
                        : "+l"(acc[s][r]) : "l"(a2), "l"(b2[r]));
                }
            }
        }
        __syncthreads();
    }

    // ---- epilogue: unpack and store ----
    #pragma unroll
    for (int s = 0; s < 4; ++s) {
        const int m = ty * 8 + 2 * s;
        float* orow0 = out + (size_t)(b0 + m) * FEAT + i0 + tx;
        float* orow1 = orow0 + FEAT;
        #pragma unroll
        for (int r = 0; r < 8; ++r) {
            float lo, hi;
            asm("mov.b64 {%0, %1}, %2;" : "=f"(lo), "=f"(hi) : "l"(acc[s][r]));
            orow0[16 * r] = lo;
            orow1[16 * r] = hi;
        }
    }
}

extern "C" void kernel_launch(void* const* d_in, const int* in_sizes, int n_in,
                              void* d_out, int out_size)
{
    const float* x    = (const float*)d_in[0];   // [2048, 4096] fp32
    const float* kern = (const float*)d_in[1];   // [4096] fp32
    float* out = (float*)d_out;                  // [2048, 4096] fp32

    dim3 block(16, 16);
    dim3 grid(FEAT / TI, BATCH / TB);            // (32, 16)
    toeplitz_gemm_kernel<<<grid, block>>>(x, kern, out);
}

// round 5
// speedup vs baseline: 2.9773x; 2.9773x over previous
#include <cuda_runtime.h>
#include <cstdint>

#define FEAT  4096
#define BATCH 2048
#define GUARD 128

// ---- dynamic SMEM layout (bytes) ----
#define KSH_OFF   0                       // (GUARD+FEAT) floats = 16896 B
#define A_OFF     17152                   // 128-aligned; 3 bufs x 16384 B
#define A_BYTES   16384
#define SMEM_TOTAL (A_OFF + 3 * A_BYTES)  // 66304 B

__device__ __forceinline__ uint32_t smem_u32(const void* p) {
    uint32_t a;
    asm("{ .reg .u64 t; cvta.to.shared.u64 t, %1; cvt.u32.u64 %0, t; }" : "=r"(a) : "l"(p));
    return a;
}
__device__ __forceinline__ uint32_t f2tf32(float f) {
    uint32_t u;
    asm("cvt.rna.tf32.f32 %0, %1;" : "=r"(u) : "f"(f));
    return u;
}
__device__ __forceinline__ void mma_tf32(float* c, const uint32_t* a, const uint32_t* b) {
    asm volatile(
        "mma.sync.aligned.m16n8k8.row.col.f32.tf32.tf32.f32 "
        "{%0,%1,%2,%3}, {%4,%5,%6,%7}, {%8,%9}, {%0,%1,%2,%3};"
        : "+f"(c[0]), "+f"(c[1]), "+f"(c[2]), "+f"(c[3])
        : "r"(a[0]), "r"(a[1]), "r"(a[2]), "r"(a[3]), "r"(b[0]), "r"(b[1]));
}
#define CP_ASYNC16(dst, src) \
    asm volatile("cp.async.ca.shared.global [%0], [%1], 16;" :: "r"(dst), "l"(src) : "memory")
#define CP_COMMIT()  asm volatile("cp.async.commit_group;" ::: "memory")
#define CP_WAIT(n)   asm volatile("cp.async.wait_group %0;" :: "n"(n) : "memory")

__global__ __launch_bounds__(256, 2)
void toep_mma(const float* __restrict__ x, const float* __restrict__ kern,
              float* __restrict__ out)
{
    extern __shared__ __align__(128) char smem[];
    float*    ksh  = (float*)(smem + KSH_OFF);      // tf32-rounded kernel + zero guard
    uint32_t* kshu = (uint32_t*)ksh;

    const int tid  = threadIdx.x;
    const int wid  = tid >> 5, lane = tid & 31;
    const int g    = lane >> 2, tg = lane & 3;      // groupID, thread-in-group

    const int it = 31 - (int)blockIdx.x;            // heavy i-tiles first
    const int i0 = it << 7;
    const int b0 = (int)blockIdx.y << 7;
    const int nchunk = (it + 1) << 2;               // K chunks of 32 up to i0+128

    // warp tile: 64(m) x 32(n); 2 warp-rows x 4 warp-cols
    const int m0 = (wid & 1) << 6;
    const int n0 = (wid >> 1) << 5;

    // ---- fill ksh: zero guard + tf32-rounded kernel ----
    if (tid < GUARD) ksh[tid] = 0.0f;
    {
        const float4* src = (const float4*)kern;
        uint4* dst = (uint4*)(ksh + GUARD);
        #pragma unroll
        for (int t = 0; t < 4; ++t) {
            float4 v = src[tid + (t << 8)];
            uint4 u;
            u.x = f2tf32(v.x); u.y = f2tf32(v.y); u.z = f2tf32(v.z); u.w = f2tf32(v.w);
            dst[tid + (t << 8)] = u;
        }
    }

    // ---- A staging: x tile 128 rows x 32 k, xor-swizzled, cp.async ----
    const int arow = tid >> 1;                       // 0..127
    const int aq0  = (tid & 1) << 2;                 // float4 index base: 0 or 4
    const float* xrow = x + (size_t)(b0 + arow) * FEAT;
    const uint32_t asw = (uint32_t)((arow & 7) << 2);
    const uint32_t abase = smem_u32(smem + A_OFF);

    // issue chunk ci into buffer ci%3
    auto issue = [&](int ci) {
        const uint32_t dstb = abase + (uint32_t)(ci % 3) * A_BYTES;
        const float* srcb = xrow + (ci << 5);
        #pragma unroll
        for (int q = 0; q < 4; ++q) {
            const uint32_t c4 = (uint32_t)((aq0 + q) << 2);         // word col base
            const uint32_t w  = (uint32_t)(arow << 5) + (c4 ^ asw); // word index
            CP_ASYNC16(dstb + (w << 2), srcb + c4);
        }
    };

    #pragma unroll
    for (int p = 0; p < 3; ++p) {                    // prologue (nchunk >= 4)
        issue(p);
        CP_COMMIT();
    }
    __syncthreads();                                  // ksh visible to all

    float acc[4][4][4];
    #pragma unroll
    for (int mf = 0; mf < 4; ++mf)
        #pragma unroll
        for (int nf = 0; nf < 4; ++nf)
            #pragma unroll
            for (int r = 0; r < 4; ++r) acc[mf][nf][r] = 0.0f;

    for (int ci = 0; ci < nchunk; ++ci) {
        CP_WAIT(2);                                   // chunk ci landed
        __syncthreads();

        const float* As = (const float*)(smem + A_OFF + (ci % 3) * A_BYTES);
        const int kc = ci << 5;

        #pragma unroll
        for (int s = 0; s < 4; ++s) {                 // 4 x k=8 steps
            // A fragments (conflict-free swizzled LDS), cvt to tf32
            uint32_t a[4][4];
            #pragma unroll
            for (int mf = 0; mf < 4; ++mf) {
                const int r0 = m0 + (mf << 4) + g;
                const int sw = (r0 & 7) << 2;
                const int c0 = (s << 3) + tg;
                a[mf][0] = f2tf32(As[(r0 << 5)       + (c0 ^ sw)]);
                a[mf][1] = f2tf32(As[((r0 + 8) << 5) + (c0 ^ sw)]);
                a[mf][2] = f2tf32(As[(r0 << 5)       + ((c0 + 4) ^ sw)]);
                a[mf][3] = f2tf32(As[((r0 + 8) << 5) + ((c0 + 4) ^ sw)]);
            }
            // B fragments straight from guarded Toeplitz kernel:
            // B[k][n] = kern[i0+n - (kc+k)];  b0: k=8s+tg, n=n0+8nf+g; b1: k += 4
            uint32_t b[4][2];
            const int bidx0 = GUARD + i0 + n0 + g - kc - (s << 3) - tg;
            #pragma unroll
            for (int nf = 0; nf < 4; ++nf) {
                b[nf][0] = kshu[bidx0 + (nf << 3)];
                b[nf][1] = kshu[bidx0 + (nf << 3) - 4];
            }
            #pragma unroll
            for (int mf = 0; mf < 4; ++mf)
                #pragma unroll
                for (int nf = 0; nf < 4; ++nf)
                    mma_tf32(acc[mf][nf], a[mf], b[nf]);
        }

        __syncthreads();                              // all reads of buf done
        if (ci + 3 < nchunk) issue(ci + 3);
        CP_COMMIT();                                  // keep group count aligned
    }

    // ---- epilogue: acc -> gmem ----
    // c0,c1: (row g, cols 2tg,2tg+1); c2,c3: row g+8
    #pragma unroll
    for (int mf = 0; mf < 4; ++mf) {
        const int row = b0 + m0 + (mf << 4) + g;
        float* o0 = out + (size_t)row * FEAT + i0 + n0 + (tg << 1);
        float* o1 = o0 + 8 * FEAT;
        #pragma unroll
        for (int nf = 0; nf < 4; ++nf) {
            *(float2*)(o0 + (nf << 3)) = make_float2(acc[mf][nf][0], acc[mf][nf][1]);
            *(float2*)(o1 + (nf << 3)) = make_float2(acc[mf][nf][2], acc[mf][nf][3]);
        }
    }
}

extern "C" void kernel_launch(void* const* d_in, const int* in_sizes, int n_in,
                              void* d_out, int out_size)
{
    const float* x    = (const float*)d_in[0];   // [2048, 4096] fp32
    const float* kern = (const float*)d_in[1];   // [4096] fp32
    float* out = (float*)d_out;                  // [2048, 4096] fp32

    cudaFuncSetAttribute(toep_mma, cudaFuncAttributeMaxDynamicSharedMemorySize, SMEM_TOTAL);
    dim3 grid(32, 16);                           // 32 feature tiles x 16 batch tiles
    toep_mma<<<grid, 256, SMEM_TOTAL>>>(x, kern, out);
}

// round 6
// speedup vs baseline: 3.9946x; 1.3417x over previous
#include <cuda_runtime.h>
#include <cstdint>

#define FEAT  4096
#define BATCH 2048
#define GUARD 128

// ---- dynamic SMEM layout (bytes) ----
#define KSH_OFF   0                       // (GUARD+FEAT) floats = 16896 B
#define A_OFF     17152                   // 128-aligned; 3 bufs x 16384 B
#define A_BYTES   16384
#define SMEM_TOTAL (A_OFF + 3 * A_BYTES)  // 66304 B

__device__ __forceinline__ uint32_t smem_u32(const void* p) {
    uint32_t a;
    asm("{ .reg .u64 t; cvta.to.shared.u64 t, %1; cvt.u32.u64 %0, t; }" : "=r"(a) : "l"(p));
    return a;
}
__device__ __forceinline__ uint32_t f2tf32(float f) {
    uint32_t u;
    asm("cvt.rna.tf32.f32 %0, %1;" : "=r"(u) : "f"(f));
    return u;
}
__device__ __forceinline__ void mma_tf32(float* c, const uint32_t* a, uint32_t b0, uint32_t b1) {
    asm volatile(
        "mma.sync.aligned.m16n8k8.row.col.f32.tf32.tf32.f32 "
        "{%0,%1,%2,%3}, {%4,%5,%6,%7}, {%8,%9}, {%0,%1,%2,%3};"
        : "+f"(c[0]), "+f"(c[1]), "+f"(c[2]), "+f"(c[3])
        : "r"(a[0]), "r"(a[1]), "r"(a[2]), "r"(a[3]), "r"(b0), "r"(b1));
}
#define CP_ASYNC16(dst, src) \
    asm volatile("cp.async.ca.shared.global [%0], [%1], 16;" :: "r"(dst), "l"(src) : "memory")
#define CP_COMMIT()  asm volatile("cp.async.commit_group;" ::: "memory")
#define CP_WAIT(n)   asm volatile("cp.async.wait_group %0;" :: "n"(n) : "memory")

__global__ __launch_bounds__(256, 2)
void toep_mma2(const float* __restrict__ x, const float* __restrict__ kern,
               float* __restrict__ out)
{
    extern __shared__ __align__(128) char smem[];
    float*    ksh  = (float*)(smem + KSH_OFF);      // tf32-rounded kernel + zero guard
    uint32_t* kshu = (uint32_t*)ksh;

    const int tid  = threadIdx.x;
    const int wid  = tid >> 5, lane = tid & 31;
    const int g    = lane >> 2, tg = lane & 3;      // groupID, thread-in-group

    const int bx = (int)blockIdx.x;                 // 0..15 -> tile pair (31-bx, bx)
    const int b0 = (int)blockIdx.y << 7;

    // warp tile: 64(m) x 32(n); 2 warp-rows x 4 warp-cols
    const int m0 = (wid & 1) << 6;
    const int n0 = (wid >> 1) << 5;

    // ---- fill ksh: zero guard + tf32-rounded kernel (once) ----
    if (tid < GUARD) ksh[tid] = 0.0f;
    {
        const float4* src = (const float4*)kern;
        uint4* dst = (uint4*)(ksh + GUARD);
        #pragma unroll
        for (int t = 0; t < 4; ++t) {
            float4 v = src[tid + (t << 8)];
            uint4 u;
            u.x = f2tf32(v.x); u.y = f2tf32(v.y); u.z = f2tf32(v.z); u.w = f2tf32(v.w);
            dst[tid + (t << 8)] = u;
        }
    }

    // ---- A staging params: x tile 128 rows x 32 k, xor-swizzled ----
    const int arow = tid >> 1;                       // 0..127
    const int aq0  = (tid & 1) << 2;                 // float4 index base: 0 or 4
    const float* xrow = x + (size_t)(b0 + arow) * FEAT;
    const uint32_t asw = (uint32_t)((arow & 7) << 2);
    const uint32_t abase = smem_u32(smem + A_OFF);

    __syncthreads();                                  // ksh visible to all

    // A-fragment addressing constants (warp-invariant across chunks)
    const int swA = g << 2;                           // (r0&7)<<2 == g<<2
    int rb[4];
    #pragma unroll
    for (int mf = 0; mf < 4; ++mf) rb[mf] = (m0 + (mf << 4) + g) << 5;

    for (int half = 0; half < 2; ++half) {
        const int it = half ? bx : 31 - bx;           // heavy tile first
        const int i0 = it << 7;
        const int nchunk = (it + 1) << 2;             // >= 4

        // issue chunk ci into buffer ci%3
        auto issue = [&](int ci) {
            const uint32_t dstb = abase + (uint32_t)(ci % 3) * A_BYTES;
            const float* srcb = xrow + (ci << 5);
            #pragma unroll
            for (int q = 0; q < 4; ++q) {
                const uint32_t c4 = (uint32_t)((aq0 + q) << 2);
                const uint32_t w  = (uint32_t)(arow << 5) + (c4 ^ asw);
                CP_ASYNC16(dstb + (w << 2), srcb + c4);
            }
        };

        #pragma unroll
        for (int p = 0; p < 3; ++p) { issue(p); CP_COMMIT(); }

        // B shift-register init (global k-step t=0):
        // V(t,nf) = kshu[bptr0 - 8t + 8nf], pair partner at -4
        int bptr = GUARD + i0 + n0 + g - tg;
        uint32_t b00 = kshu[bptr],      b01 = kshu[bptr - 4];
        uint32_t b10 = kshu[bptr + 8],  b11 = kshu[bptr + 4];
        uint32_t b20 = kshu[bptr + 16], b21 = kshu[bptr + 12];
        uint32_t b30 = kshu[bptr + 24], b31 = kshu[bptr + 20];

        float acc[4][4][4];
        #pragma unroll
        for (int mf = 0; mf < 4; ++mf)
            #pragma unroll
            for (int nf = 0; nf < 4; ++nf)
                #pragma unroll
                for (int r = 0; r < 4; ++r) acc[mf][nf][r] = 0.0f;

        for (int ci = 0; ci < nchunk; ++ci) {
            CP_WAIT(2);                               // chunk ci landed
            __syncthreads();

            const uint32_t* As = (const uint32_t*)(smem + A_OFF + (ci % 3) * A_BYTES);

            #pragma unroll
            for (int s = 0; s < 4; ++s) {
                const int o1 = ((s << 3) + tg) ^ swA;
                const int o2 = ((s << 3) + tg + 4) ^ swA;
                uint32_t a[4][4];
                #pragma unroll
                for (int mf = 0; mf < 4; ++mf) {
                    a[mf][0] = As[rb[mf] + o1];
                    a[mf][1] = As[rb[mf] + 256 + o1];   // +8 rows
                    a[mf][2] = As[rb[mf] + o2];
                    a[mf][3] = As[rb[mf] + 256 + o2];
                }
                mma_tf32(acc[0][0], a[0], b00, b01);
                mma_tf32(acc[1][0], a[1], b00, b01);
                mma_tf32(acc[2][0], a[2], b00, b01);
                mma_tf32(acc[3][0], a[3], b00, b01);
                mma_tf32(acc[0][1], a[0], b10, b11);
                mma_tf32(acc[1][1], a[1], b10, b11);
                mma_tf32(acc[2][1], a[2], b10, b11);
                mma_tf32(acc[3][1], a[3], b10, b11);
                mma_tf32(acc[0][2], a[0], b20, b21);
                mma_tf32(acc[1][2], a[1], b20, b21);
                mma_tf32(acc[2][2], a[2], b20, b21);
                mma_tf32(acc[3][2], a[3], b20, b21);
                mma_tf32(acc[0][3], a[0], b30, b31);
                mma_tf32(acc[1][3], a[1], b30, b31);
                mma_tf32(acc[2][3], a[2], b30, b31);
                mma_tf32(acc[3][3], a[3], b30, b31);
                // shift register: V(t+1,nf) = V(t,nf-1); 2 new LDS
                b30 = b20; b31 = b21;
                b20 = b10; b21 = b11;
                b10 = b00; b11 = b01;
                bptr -= 8;
                b00 = kshu[bptr]; b01 = kshu[bptr - 4];
            }

            __syncthreads();                          // all reads of buf done
            if (ci + 3 < nchunk) issue(ci + 3);
            CP_COMMIT();                              // keep group count aligned
        }
        CP_WAIT(0);                                   // drain empties before next tile

        // ---- epilogue for this tile ----
        #pragma unroll
        for (int mf = 0; mf < 4; ++mf) {
            const int row = b0 + m0 + (mf << 4) + g;
            float* o0 = out + (size_t)row * FEAT + i0 + n0 + (tg << 1);
            float* o1 = o0 + 8 * FEAT;
            #pragma unroll
            for (int nf = 0; nf < 4; ++nf) {
                *(float2*)(o0 + (nf << 3)) = make_float2(acc[mf][nf][0], acc[mf][nf][1]);
                *(float2*)(o1 + (nf << 3)) = make_float2(acc[mf][nf][2], acc[mf][nf][3]);
            }
        }
    }
}

extern "C" void kernel_launch(void* const* d_in, const int* in_sizes, int n_in,
                              void* d_out, int out_size)
{
    const float* x    = (const float*)d_in[0];   // [2048, 4096] fp32
    const float* kern = (const float*)d_in[1];   // [4096] fp32
    float* out = (float*)d_out;                  // [2048, 4096] fp32

    cudaFuncSetAttribute(toep_mma2, cudaFuncAttributeMaxDynamicSharedMemorySize, SMEM_TOTAL);
    dim3 grid(16, 16);                           // 16 balanced tile-pairs x 16 batch tiles
    toep_mma2<<<grid, 256, SMEM_TOTAL>>>(x, kern, out);
}

// round 8
// speedup vs baseline: 4.7492x; 1.1889x over previous
#include <cuda_runtime.h>
#include <cstdint>

#define FEAT  4096
#define BATCH 2048
#define GUARD 128

// ---- dynamic SMEM layout (bytes) ----
#define KSH_OFF   0                       // (GUARD+FEAT) floats = 16896 B
#define A_OFF     17152                   // 128-aligned; 3 bufs x 16384 B
#define A_BYTES   16384
#define SMEM_TOTAL (A_OFF + 3 * A_BYTES)  // 66304 B

__device__ __forceinline__ uint32_t smem_u32(const void* p) {
    uint32_t a;
    asm("{ .reg .u64 t; cvta.to.shared.u64 t, %1; cvt.u32.u64 %0, t; }" : "=r"(a) : "l"(p));
    return a;
}
__device__ __forceinline__ uint32_t f2tf32(float f) {
    uint32_t u;
    asm("cvt.rna.tf32.f32 %0, %1;" : "=r"(u) : "f"(f));
    return u;
}
__device__ __forceinline__ void mma_tf32(float* c, const uint32_t* a, uint32_t b0, uint32_t b1) {
    asm volatile(
        "mma.sync.aligned.m16n8k8.row.col.f32.tf32.tf32.f32 "
        "{%0,%1,%2,%3}, {%4,%5,%6,%7}, {%8,%9}, {%0,%1,%2,%3};"
        : "+f"(c[0]), "+f"(c[1]), "+f"(c[2]), "+f"(c[3])
        : "r"(a[0]), "r"(a[1]), "r"(a[2]), "r"(a[3]), "r"(b0), "r"(b1));
}
#define CP_ASYNC16(dst, src) \
    asm volatile("cp.async.cg.shared.global [%0], [%1], 16;" :: "r"(dst), "l"(src) : "memory")
#define CP_COMMIT()  asm volatile("cp.async.commit_group;" ::: "memory")
#define CP_WAIT(n)   asm volatile("cp.async.wait_group %0;" :: "n"(n) : "memory")

__global__ __launch_bounds__(256, 2)
void toep_mma3(const float* __restrict__ x, const float* __restrict__ kern,
               float* __restrict__ out)
{
    extern __shared__ __align__(128) char smem[];
    float*    ksh  = (float*)(smem + KSH_OFF);      // tf32-rounded kernel + zero guard
    uint32_t* kshu = (uint32_t*)ksh;

    const int tid  = threadIdx.x;
    const int wid  = tid >> 5, lane = tid & 31;
    const int g    = lane >> 2, tg = lane & 3;      // groupID, thread-in-group

    const int bx = (int)blockIdx.x;                 // 0..15 -> tile pair (31-bx, bx)
    const int b0 = (int)blockIdx.y << 7;

    // warp tile: 32(m) x 64(n); 4 m-warps x 2 n-warps
    const int m0 = (wid & 3) << 5;
    const int n0 = (wid >> 2) << 6;

    // ---- fill ksh: zero guard + tf32-rounded kernel (once) ----
    if (tid < GUARD) ksh[tid] = 0.0f;
    {
        const float4* src = (const float4*)kern;
        uint4* dst = (uint4*)(ksh + GUARD);
        #pragma unroll
        for (int t = 0; t < 4; ++t) {
            float4 v = src[tid + (t << 8)];
            uint4 u;
            u.x = f2tf32(v.x); u.y = f2tf32(v.y); u.z = f2tf32(v.z); u.w = f2tf32(v.w);
            dst[tid + (t << 8)] = u;
        }
    }

    // ---- A staging params: x tile 128 rows x 32 k, xor-swizzled ----
    const int arow = tid >> 1;                       // 0..127
    const int aq0  = (tid & 1) << 2;                 // float4 index base: 0 or 4
    const float* xrow = x + (size_t)(b0 + arow) * FEAT;
    const uint32_t asw = (uint32_t)((arow & 7) << 2);
    const uint32_t abase = smem_u32(smem + A_OFF);

    __syncthreads();                                  // ksh visible to all

    // A-fragment addressing constants
    const int swA = g << 2;
    int rb[2];
    #pragma unroll
    for (int mf = 0; mf < 2; ++mf) rb[mf] = (m0 + (mf << 4) + g) << 5;

    for (int half = 0; half < 2; ++half) {
        const int it = half ? bx : 31 - bx;           // heavy tile first
        const int i0 = it << 7;
        const int nchunk = (it + 1) << 2;             // >= 4

        if (half) __syncthreads();                    // bufs free before refill

        auto issue = [&](int ci) {
            const uint32_t dstb = abase + (uint32_t)(ci % 3) * A_BYTES;
            const float* srcb = xrow + (ci << 5);
            #pragma unroll
            for (int q = 0; q < 4; ++q) {
                const uint32_t c4 = (uint32_t)((aq0 + q) << 2);
                const uint32_t w  = (uint32_t)(arow << 5) + (c4 ^ asw);
                CP_ASYNC16(dstb + (w << 2), srcb + c4);
            }
        };

        issue(0); CP_COMMIT();
        issue(1); CP_COMMIT();

        // B shift register over 8 n-fragments:
        // V(t,nf) = kshu[G+i0+n0+g-tg - 8t + 8nf], partner at -4
        int bptr = GUARD + i0 + n0 + g - tg;
        uint32_t bv0[8], bv1[8];
        #pragma unroll
        for (int nf = 0; nf < 8; ++nf) {
            bv0[nf] = kshu[bptr + (nf << 3)];
            bv1[nf] = kshu[bptr + (nf << 3) - 4];
        }

        float acc[2][8][4];
        #pragma unroll
        for (int mf = 0; mf < 2; ++mf)
            #pragma unroll
            for (int nf = 0; nf < 8; ++nf)
                #pragma unroll
                for (int r = 0; r < 4; ++r) acc[mf][nf][r] = 0.0f;

        for (int ci = 0; ci < nchunk; ++ci) {
            CP_WAIT(1);                               // chunk ci landed
            __syncthreads();                          // visible; buf (ci-1)%3 free
            if (ci + 2 < nchunk) issue(ci + 2);
            CP_COMMIT();                              // keep group/chunk alignment

            const uint32_t* As = (const uint32_t*)(smem + A_OFF + (ci % 3) * A_BYTES);

            #pragma unroll
            for (int s = 0; s < 4; ++s) {
                const int o1 = ((s << 3) + tg) ^ swA;
                const int o2 = o1 ^ 4;
                uint32_t a[2][4];
                #pragma unroll
                for (int mf = 0; mf < 2; ++mf) {
                    a[mf][0] = As[rb[mf] + o1];
                    a[mf][1] = As[rb[mf] + 256 + o1];   // +8 rows
                    a[mf][2] = As[rb[mf] + o2];
                    a[mf][3] = As[rb[mf] + 256 + o2];
                }
                #pragma unroll
                for (int nf = 0; nf < 8; ++nf) {
                    mma_tf32(acc[0][nf], a[0], bv0[nf], bv1[nf]);
                    mma_tf32(acc[1][nf], a[1], bv0[nf], bv1[nf]);
                }
                // shift: V(t+1,nf) = V(t,nf-1); refill nf=0 (2 LDS)
                #pragma unroll
                for (int nf = 7; nf > 0; --nf) { bv0[nf] = bv0[nf - 1]; bv1[nf] = bv1[nf - 1]; }
                bptr -= 8;
                bv0[0] = kshu[bptr]; bv1[0] = kshu[bptr - 4];
            }
        }
        CP_WAIT(0);

        // ---- epilogue for this tile ----
        #pragma unroll
        for (int mf = 0; mf < 2; ++mf) {
            const int row = b0 + m0 + (mf << 4) + g;
            float* o0 = out + (size_t)row * FEAT + i0 + n0 + (tg << 1);
            float* o1 = o0 + 8 * FEAT;
            #pragma unroll
            for (int nf = 0; nf < 8; ++nf) {
                *(float2*)(o0 + (nf << 3)) = make_float2(acc[mf][nf][0], acc[mf][nf][1]);
                *(float2*)(o1 + (nf << 3)) = make_float2(acc[mf][nf][2], acc[mf][nf][3]);
            }
        }
    }
}

extern "C" void kernel_launch(void* const* d_in, const int* in_sizes, int n_in,
                              void* d_out, int out_size)
{
    const float* x    = (const float*)d_in[0];   // [2048, 4096] fp32
    const float* kern = (const float*)d_in[1];   // [4096] fp32
    float* out = (float*)d_out;                  // [2048, 4096] fp32

    cudaFuncSetAttribute(toep_mma3, cudaFuncAttributeMaxDynamicSharedMemorySize, SMEM_TOTAL);
    dim3 grid(16, 16);                           // 16 balanced tile-pairs x 16 batch tiles
    toep_mma3<<<grid, 256, SMEM_TOTAL>>>(x, kern, out);
}

// round 11
// speedup vs baseline: 4.9020x; 1.0322x over previous
#include <cuda_runtime.h>
#include <cstdint>

#define FEAT  4096
#define BATCH 2048
#define GUARD 128

// ---- dynamic SMEM layout (bytes) ----
#define KSH_OFF   0                       // (GUARD+FEAT) floats = 16896 B
#define A_OFF     17152                   // 128-aligned; 3 superbufs x 32768 B
#define A_BYTES   32768                   // 128 rows x 64 cols fp32 (two 16KB halves)
#define SMEM_TOTAL (A_OFF + 3 * A_BYTES)  // 115456 B

__device__ __forceinline__ uint32_t smem_u32(const void* p) {
    uint32_t a;
    asm("{ .reg .u64 t; cvta.to.shared.u64 t, %1; cvt.u32.u64 %0, t; }" : "=r"(a) : "l"(p));
    return a;
}
__device__ __forceinline__ uint32_t f2tf32(float f) {
    uint32_t u;
    asm("cvt.rna.tf32.f32 %0, %1;" : "=r"(u) : "f"(f));
    return u;
}
__device__ __forceinline__ void mma_tf32(float* c, const uint32_t* a, uint32_t b0, uint32_t b1) {
    asm volatile(
        "mma.sync.aligned.m16n8k8.row.col.f32.tf32.tf32.f32 "
        "{%0,%1,%2,%3}, {%4,%5,%6,%7}, {%8,%9}, {%0,%1,%2,%3};"
        : "+f"(c[0]), "+f"(c[1]), "+f"(c[2]), "+f"(c[3])
        : "r"(a[0]), "r"(a[1]), "r"(a[2]), "r"(a[3]), "r"(b0), "r"(b1));
}
__device__ __forceinline__ void ldsm_x4(uint32_t* r, uint32_t addr) {
    asm volatile("ldmatrix.sync.aligned.m8n8.x4.shared.b16 {%0,%1,%2,%3}, [%4];"
        : "=r"(r[0]), "=r"(r[1]), "=r"(r[2]), "=r"(r[3]) : "r"(addr));
}
#define CP_ASYNC16(dst, src) \
    asm volatile("cp.async.cg.shared.global [%0], [%1], 16;" :: "r"(dst), "l"(src) : "memory")
#define CP_COMMIT()  asm volatile("cp.async.commit_group;" ::: "memory")
#define CP_WAIT(n)   asm volatile("cp.async.wait_group %0;" :: "n"(n) : "memory")

__global__ __launch_bounds__(256, 2)
void toep_mma4(const float* __restrict__ x, const float* __restrict__ kern,
               float* __restrict__ out)
{
    extern __shared__ __align__(128) char smem[];
    float*    ksh  = (float*)(smem + KSH_OFF);      // tf32-rounded kernel + zero guard
    uint32_t* kshu = (uint32_t*)ksh;

    const int tid  = threadIdx.x;
    const int wid  = tid >> 5, lane = tid & 31;
    const int g    = lane >> 2, tg = lane & 3;      // groupID, thread-in-group

    const int bx = (int)blockIdx.x;                 // 0..15 -> tile pair (31-bx, bx)
    const int b0 = (int)blockIdx.y << 7;

    // warp tile: 32(m) x 64(n); 4 m-warps x 2 n-warps
    const int m0 = (wid & 3) << 5;
    const int n0 = (wid >> 2) << 6;

    // ---- fill ksh: zero guard + tf32-rounded kernel (once) ----
    if (tid < GUARD) ksh[tid] = 0.0f;
    {
        const float4* src = (const float4*)kern;
        uint4* dst = (uint4*)(ksh + GUARD);
        #pragma unroll
        for (int t = 0; t < 4; ++t) {
            float4 v = src[tid + (t << 8)];
            uint4 u;
            u.x = f2tf32(v.x); u.y = f2tf32(v.y); u.z = f2tf32(v.z); u.w = f2tf32(v.w);
            dst[tid + (t << 8)] = u;
        }
    }

    // ---- A staging params: 128 rows x 64 cols per superchunk, xor-swizzled halves ----
    const int arow = tid >> 1;                       // 0..127
    const int aq0  = (tid & 1) << 2;                 // float4 index base: 0 or 4
    const float* xrow = x + (size_t)(b0 + arow) * FEAT;
    const uint32_t asw = (uint32_t)((arow & 7) << 2);
    const uint32_t abase = smem_u32(smem + A_OFF);

    __syncthreads();                                  // ksh visible to all

    // ldmatrix lane addressing: lane<16 -> cols 0-3, lane>=16 -> cols 4-7
    const int lrow = lane & 15;                       // row within 16-row fragment
    const int c0l  = (lane < 16) ? 0 : 4;
    int rbase[2], swl[2];
    #pragma unroll
    for (int mf = 0; mf < 2; ++mf) {
        const int rf = m0 + (mf << 4) + lrow;
        rbase[mf] = rf << 5;                          // word offset of row
        swl[mf]   = (rf & 7) << 2;
    }

    for (int half = 0; half < 2; ++half) {
        const int it = half ? bx : 31 - bx;           // heavy tile first
        const int i0 = it << 7;
        const int nsc = (it + 1) << 1;                // superchunks of 64 k, >= 2

        if (half) __syncthreads();                    // bufs free before refill

        auto issue = [&](int sc) {
            const uint32_t dstb = abase + (uint32_t)(sc % 3) * A_BYTES;
            const float* srcb = xrow + (sc << 6);
            #pragma unroll
            for (int h = 0; h < 2; ++h)
                #pragma unroll
                for (int q = 0; q < 4; ++q) {
                    const uint32_t c4 = (uint32_t)((aq0 + q) << 2);
                    const uint32_t w  = (uint32_t)(arow << 5) + (c4 ^ asw);
                    CP_ASYNC16(dstb + (uint32_t)(h << 14) + (w << 2), srcb + (h << 5) + c4);
                }
        };

        issue(0); CP_COMMIT();
        issue(1); CP_COMMIT();

        // B circular registers: bv[w] = kshu[bptr + 8w] (w = (nf - T) & 7)
        int bptr = GUARD + i0 + n0 + g - tg;
        uint32_t bv0[8], bv1[8];
        #pragma unroll
        for (int w = 0; w < 8; ++w) {
            bv0[w] = kshu[bptr + (w << 3)];
            bv1[w] = kshu[bptr + (w << 3) - 4];
        }

        float acc[2][8][4];
        #pragma unroll
        for (int mf = 0; mf < 2; ++mf)
            #pragma unroll
            for (int nf = 0; nf < 8; ++nf)
                #pragma unroll
                for (int r = 0; r < 4; ++r) acc[mf][nf][r] = 0.0f;

        for (int sc = 0; sc < nsc; ++sc) {
            CP_WAIT(1);                               // superchunk sc landed
            __syncthreads();                          // visible; buf (sc-1)%3 free
            if (sc + 2 < nsc) issue(sc + 2);
            CP_COMMIT();                              // keep group/sc alignment

            const uint32_t bufb = abase + (uint32_t)(sc % 3) * A_BYTES;

            #pragma unroll
            for (int T = 0; T < 8; ++T) {
                const uint32_t hb = bufb + (uint32_t)((T >> 2) << 14);
                const int u = ((T & 3) << 3) | c0l;
                uint32_t a[2][4];
                ldsm_x4(a[0], hb + (uint32_t)((rbase[0] + (u ^ swl[0])) << 2));
                ldsm_x4(a[1], hb + (uint32_t)((rbase[1] + (u ^ swl[1])) << 2));
                #pragma unroll
                for (int nf = 0; nf < 8; ++nf) {
                    const int w = (nf - T) & 7;
                    mma_tf32(acc[0][nf], a[0], bv0[w], bv1[w]);
                    mma_tf32(acc[1][nf], a[1], bv0[w], bv1[w]);
                }
                const int wr = (7 - T) & 7;           // refill for next step
                bv0[wr] = kshu[bptr - 8];
                bv1[wr] = kshu[bptr - 12];
                bptr -= 8;
            }
        }
        CP_WAIT(0);

        // ---- epilogue for this tile ----
        #pragma unroll
        for (int mf = 0; mf < 2; ++mf) {
            const int row = b0 + m0 + (mf << 4) + g;
            float* o0 = out + (size_t)row * FEAT + i0 + n0 + (tg << 1);
            float* o1 = o0 + 8 * FEAT;
            #pragma unroll
            for (int nf = 0; nf < 8; ++nf) {
                *(float2*)(o0 + (nf << 3)) = make_float2(acc[mf][nf][0], acc[mf][nf][1]);
                *(float2*)(o1 + (nf << 3)) = make_float2(acc[mf][nf][2], acc[mf][nf][3]);
            }
        }
    }
}

extern "C" void kernel_launch(void* const* d_in, const int* in_sizes, int n_in,
                              void* d_out, int out_size)
{
    const float* x    = (const float*)d_in[0];   // [2048, 4096] fp32
    const float* kern = (const float*)d_in[1];   // [4096] fp32
    float* out = (float*)d_out;                  // [2048, 4096] fp32

    cudaFuncSetAttribute(toep_mma4, cudaFuncAttributeMaxDynamicSharedMemorySize, SMEM_TOTAL);
    dim3 grid(16, 16);                           // 16 balanced tile-pairs x 16 batch tiles
    toep_mma4<<<grid, 256, SMEM_TOTAL>>>(x, kern, out);
}

// round 12
// speedup vs baseline: 5.1235x; 1.0452x over previous
#include <cuda_runtime.h>
#include <cstdint>

#define FEAT  4096
#define BATCH 2048
#define GUARD 128
#define KP_N  (GUARD + FEAT)              // 4224 tf32 pairs

// ---- dynamic SMEM layout (bytes) ----
#define KP_OFF  0                          // 4224 * 8 = 33792 B
#define A_OFF   33792                      // 128-aligned; 2 superbufs x 32768 B
#define A_BYTES 32768                      // 128 rows x 64 cols fp32 (two 16KB halves)
#define SMEM_TOTAL (A_OFF + 2 * A_BYTES)   // 99328 B -> 2 CTAs/SM

__device__ __forceinline__ uint32_t smem_u32(const void* p) {
    uint32_t a;
    asm("{ .reg .u64 t; cvta.to.shared.u64 t, %1; cvt.u32.u64 %0, t; }" : "=r"(a) : "l"(p));
    return a;
}
__device__ __forceinline__ uint32_t f2tf32(float f) {
    uint32_t u;
    asm("cvt.rna.tf32.f32 %0, %1;" : "=r"(u) : "f"(f));
    return u;
}
__device__ __forceinline__ void mma_tf32(float* c, const uint32_t* a, uint32_t b0, uint32_t b1) {
    asm volatile(
        "mma.sync.aligned.m16n8k8.row.col.f32.tf32.tf32.f32 "
        "{%0,%1,%2,%3}, {%4,%5,%6,%7}, {%8,%9}, {%0,%1,%2,%3};"
        : "+f"(c[0]), "+f"(c[1]), "+f"(c[2]), "+f"(c[3])
        : "r"(a[0]), "r"(a[1]), "r"(a[2]), "r"(a[3]), "r"(b0), "r"(b1));
}
__device__ __forceinline__ void ldsm_x4(uint32_t* r, uint32_t addr) {
    asm volatile("ldmatrix.sync.aligned.m8n8.x4.shared.b16 {%0,%1,%2,%3}, [%4];"
        : "=r"(r[0]), "=r"(r[1]), "=r"(r[2]), "=r"(r[3]) : "r"(addr));
}
__device__ __forceinline__ void lds_pair(uint32_t& p0, uint32_t& p1, uint32_t addr) {
    asm volatile("ld.shared.v2.b32 {%0,%1}, [%2];" : "=r"(p0), "=r"(p1) : "r"(addr));
}
#define CP_ASYNC16(dst, src) \
    asm volatile("cp.async.cg.shared.global [%0], [%1], 16;" :: "r"(dst), "l"(src) : "memory")
#define CP_COMMIT()  asm volatile("cp.async.commit_group;" ::: "memory")
#define CP_WAIT(n)   asm volatile("cp.async.wait_group %0;" :: "n"(n) : "memory")

__global__ __launch_bounds__(256, 2)
void toep_mma5(const float* __restrict__ x, const float* __restrict__ kern,
               float* __restrict__ out)
{
    extern __shared__ __align__(128) char smem[];
    uint32_t* kpw = (uint32_t*)(smem + KP_OFF);     // pair table as words: kp[i] = words 2i, 2i+1

    const int tid  = threadIdx.x;
    const int wid  = tid >> 5, lane = tid & 31;
    const int g    = lane >> 2, tg = lane & 3;

    const int bx = (int)blockIdx.x;                 // 0..15 -> tile pair (31-bx, bx)
    const int b0 = (int)blockIdx.y << 7;

    // warp tile: 32(m) x 64(n); 4 m-warps x 2 n-warps
    const int m0 = (wid & 3) << 5;
    const int n0 = (wid >> 2) << 6;

    // ---- build kp[i] = (tf32(kern[i-G]), tf32(kern[i-G-4])), zeros under guard ----
    for (int i = tid; i < KP_N; i += 256) {         // zero-fill both words
        kpw[2 * i] = 0u; kpw[2 * i + 1] = 0u;
    }
    __syncthreads();
    for (int i = tid; i < FEAT; i += 256) {
        const uint32_t u = f2tf32(kern[i]);
        kpw[2 * (GUARD + i)] = u;                   // kp[G+i].x
        if (i < FEAT - 4) kpw[2 * (GUARD + i + 4) + 1] = u;  // kp[G+i+4].y
    }

    // ---- A staging params: 128 rows x 64 cols per superchunk, xor-swizzled halves ----
    const int arow = tid >> 1;
    const int aq0  = (tid & 1) << 2;
    const float* xrow = x + (size_t)(b0 + arow) * FEAT;
    const uint32_t asw = (uint32_t)((arow & 7) << 2);
    const uint32_t abase = smem_u32(smem + A_OFF);
    const uint32_t kpb = smem_u32(smem + KP_OFF);

    __syncthreads();                                  // kp table visible

    // ldmatrix lane addressing
    const int lrow = lane & 15;
    const int c0l  = (lane < 16) ? 0 : 4;
    int rbase[2], swl[2];
    #pragma unroll
    for (int mf = 0; mf < 2; ++mf) {
        const int rf = m0 + (mf << 4) + lrow;
        rbase[mf] = rf << 5;
        swl[mf]   = (rf & 7) << 2;
    }

    for (int half = 0; half < 2; ++half) {
        const int it = half ? bx : 31 - bx;           // heavy tile first
        const int i0 = it << 7;
        const int nsc = (it + 1) << 1;                // superchunks of 64 k, >= 2

        auto issue = [&](int sc) {
            const uint32_t dstb = abase + (uint32_t)((sc & 1) ? A_BYTES : 0);
            const float* srcb = xrow + (sc << 6);
            #pragma unroll
            for (int h = 0; h < 2; ++h)
                #pragma unroll
                for (int q = 0; q < 4; ++q) {
                    const uint32_t c4 = (uint32_t)((aq0 + q) << 2);
                    const uint32_t w  = (uint32_t)(arow << 5) + (c4 ^ asw);
                    CP_ASYNC16(dstb + (uint32_t)(h << 14) + (w << 2), srcb + (h << 5) + c4);
                }
        };

        if (half) __syncthreads();                    // bufs free before refill
        issue(0); CP_COMMIT();

        // B circular registers from pair table: w = (nf - T) & 7
        int bptr = GUARD + i0 + n0 + g - tg;
        uint32_t bv0[8], bv1[8];
        #pragma unroll
        for (int w = 0; w < 8; ++w)
            lds_pair(bv0[w], bv1[w], kpb + (uint32_t)((bptr + (w << 3)) << 3));

        float acc[2][8][4];
        #pragma unroll
        for (int mf = 0; mf < 2; ++mf)
            #pragma unroll
            for (int nf = 0; nf < 8; ++nf)
                #pragma unroll
                for (int r = 0; r < 4; ++r) acc[mf][nf][r] = 0.0f;

        for (int sc = 0; sc < nsc; ++sc) {
            CP_WAIT(0);                               // superchunk sc landed
            __syncthreads();                          // all warps done with sc-1's buffer
            if (sc + 1 < nsc) { issue(sc + 1); }      // fill other buffer during compute
            CP_COMMIT();

            const uint32_t bufb = abase + (uint32_t)((sc & 1) ? A_BYTES : 0);

            // software-pipelined A fragments: parity-indexed, zero-mov unrolled
            uint32_t a[2][2][4];
            {
                const int u0 = c0l;                   // T = 0 addresses (half h=0)
                ldsm_x4(a[0][0], bufb + (uint32_t)((rbase[0] + (u0 ^ swl[0])) << 2));
                ldsm_x4(a[0][1], bufb + (uint32_t)((rbase[1] + (u0 ^ swl[1])) << 2));
            }
            #pragma unroll
            for (int T = 0; T < 8; ++T) {
                const int p = T & 1;
                if (T < 7) {                          // prefetch T+1 fragments
                    const uint32_t hb = bufb + (uint32_t)((((T + 1) >> 2) & 1) << 14);
                    const int u = (((T + 1) & 3) << 3) | c0l;
                    ldsm_x4(a[p ^ 1][0], hb + (uint32_t)((rbase[0] + (u ^ swl[0])) << 2));
                    ldsm_x4(a[p ^ 1][1], hb + (uint32_t)((rbase[1] + (u ^ swl[1])) << 2));
                }
                #pragma unroll
                for (int nf = 0; nf < 8; ++nf) {
                    const int w = (nf - T) & 7;
                    mma_tf32(acc[0][nf], a[p][0], bv0[w], bv1[w]);
                    mma_tf32(acc[1][nf], a[p][1], bv0[w], bv1[w]);
                }
                const int wr = (7 - T) & 7;           // refill slot consumed 8 steps later
                lds_pair(bv0[wr], bv1[wr], kpb + (uint32_t)((bptr - 8) << 3));
                bptr -= 8;
            }
        }
        CP_WAIT(0);

        // ---- epilogue for this tile ----
        #pragma unroll
        for (int mf = 0; mf < 2; ++mf) {
            const int row = b0 + m0 + (mf << 4) + g;
            float* o0 = out + (size_t)row * FEAT + i0 + n0 + (tg << 1);
            float* o1 = o0 + 8 * FEAT;
            #pragma unroll
            for (int nf = 0; nf < 8; ++nf) {
                *(float2*)(o0 + (nf << 3)) = make_float2(acc[mf][nf][0], acc[mf][nf][1]);
                *(float2*)(o1 + (nf << 3)) = make_float2(acc[mf][nf][2], acc[mf][nf][3]);
            }
        }
    }
}

extern "C" void kernel_launch(void* const* d_in, const int* in_sizes, int n_in,
                              void* d_out, int out_size)
{
    const float* x    = (const float*)d_in[0];   // [2048, 4096] fp32
    const float* kern = (const float*)d_in[1];   // [4096] fp32
    float* out = (float*)d_out;                  // [2048, 4096] fp32

    cudaFuncSetAttribute(toep_mma5, cudaFuncAttributeMaxDynamicSharedMemorySize, SMEM_TOTAL);
    dim3 grid(16, 16);                           // 16 balanced tile-pairs x 16 batch tiles
    toep_mma5<<<grid, 256, SMEM_TOTAL>>>(x, kern, out);
}